// round 4
// baseline (speedup 1.0000x reference)
#include <cuda_runtime.h>
#include <math.h>

// ---------------- problem constants ----------------
#define BB    2
#define NN    2048
#define DM    1024
#define NH    16
#define NKV   4
#define HD    64
#define RR    256
#define NM    1792          // N - R
#define HALF  1024          // N/2
#define MROWS (BB*NM)       // 3584
#define KVD   (NKV*HD)      // 256

// ---------------- scratch (static device memory, ~75 MB) ----------------
__device__ float g_metric[BB*NN*KVD];
__device__ float g_an [BB*HALF*KVD];
__device__ float g_bn [BB*HALF*KVD];
__device__ float g_bnT[BB*KVD*HALF];
__device__ float g_bestS[BB*HALF];
__device__ int   g_bestB[BB*HALF];
__device__ int   g_ga[BB*RR];
__device__ int   g_gb[BB*RR];
__device__ int   g_partner[BB*NN];
__device__ int   g_keep[BB*NM];
__device__ float g_xm[(size_t)MROWS*DM];
__device__ float g_q [(size_t)MROWS*DM];
__device__ float g_kb[(size_t)MROWS*KVD];
__device__ float g_v [(size_t)MROWS*KVD];
__device__ float g_o [(size_t)MROWS*DM];
__device__ float g_om[(size_t)MROWS*DM];

// ---------------- generic fp32 SGEMM: C[M,N] = A[M,K] @ B[K,N] ----------------
// row-major; requires M%128==0, N%128==0, K%16==0.
__global__ void __launch_bounds__(256)
gemm_k(const float* __restrict__ A, const float* __restrict__ B,
       float* __restrict__ C, int M, int N, int K)
{
    const int BM = 128, BN = 128, BK = 16;
    __shared__ float As[16][132];
    __shared__ float Bs[16][132];
    const int tid = threadIdx.x;
    const int tx  = tid & 15;       // 0..15 over N
    const int ty  = tid >> 4;       // 0..15 over M
    const int m0  = blockIdx.y * BM;
    const int n0  = blockIdx.x * BN;

    float acc[8][8];
    #pragma unroll
    for (int i = 0; i < 8; i++)
        #pragma unroll
        for (int j = 0; j < 8; j++) acc[i][j] = 0.f;

    for (int k0 = 0; k0 < K; k0 += BK) {
        // load A tile (128x16) transposed into As[k][m]
        #pragma unroll
        for (int i = 0; i < 2; i++) {
            int s  = tid + i * 256;            // 0..511
            int r  = s >> 2;                   // 0..127
            int kc = (s & 3) * 4;              // 0,4,8,12
            float4 v = *(const float4*)(A + (size_t)(m0 + r) * K + k0 + kc);
            As[kc + 0][r] = v.x; As[kc + 1][r] = v.y;
            As[kc + 2][r] = v.z; As[kc + 3][r] = v.w;
        }
        // load B tile (16x128)
        #pragma unroll
        for (int i = 0; i < 2; i++) {
            int s = tid + i * 256;             // 0..511
            int r = s >> 5;                    // 0..15
            int c = (s & 31) * 4;              // 0..124
            *(float4*)&Bs[r][c] = *(const float4*)(B + (size_t)(k0 + r) * N + n0 + c);
        }
        __syncthreads();
        #pragma unroll
        for (int kk = 0; kk < BK; kk++) {
            float ra[8], rb[8];
            *(float4*)&ra[0] = *(const float4*)&As[kk][ty * 8];
            *(float4*)&ra[4] = *(const float4*)&As[kk][ty * 8 + 4];
            *(float4*)&rb[0] = *(const float4*)&Bs[kk][tx * 8];
            *(float4*)&rb[4] = *(const float4*)&Bs[kk][tx * 8 + 4];
            #pragma unroll
            for (int i = 0; i < 8; i++)
                #pragma unroll
                for (int j = 0; j < 8; j++) acc[i][j] += ra[i] * rb[j];
        }
        __syncthreads();
    }
    #pragma unroll
    for (int i = 0; i < 8; i++) {
        size_t cr = (size_t)(m0 + ty * 8 + i) * N + n0 + tx * 8;
        *(float4*)(C + cr)     = make_float4(acc[i][0], acc[i][1], acc[i][2], acc[i][3]);
        *(float4*)(C + cr + 4) = make_float4(acc[i][4], acc[i][5], acc[i][6], acc[i][7]);
    }
}

// ---------------- normalize metric rows into an (even) / bn (odd) ----------------
__global__ void normalize_k()
{
    __shared__ float wsum[8];
    __shared__ float total;
    int row = blockIdx.x, t = threadIdx.x;
    float v = g_metric[(size_t)row * KVD + t];
    float ss = v * v;
    #pragma unroll
    for (int o = 16; o; o >>= 1) ss += __shfl_xor_sync(0xffffffffu, ss, o);
    if ((t & 31) == 0) wsum[t >> 5] = ss;
    __syncthreads();
    if (t == 0) {
        float s2 = 0.f;
        #pragma unroll
        for (int i = 0; i < 8; i++) s2 += wsum[i];
        total = fmaxf(sqrtf(s2), 1e-12f);
    }
    __syncthreads();
    float outv = v / total;
    int b = row >> 11, i = row & 2047;
    if (i & 1) g_bn[((size_t)b * HALF + (i >> 1)) * KVD + t] = outv;
    else       g_an[((size_t)b * HALF + (i >> 1)) * KVD + t] = outv;
}

// ---------------- transpose bn (1024x256) -> bnT (256x1024) per batch ----------------
__global__ void transpose_k()
{
    __shared__ float tile[32][33];
    int b  = blockIdx.z;
    int j0 = blockIdx.x * 32;   // token dim
    int d0 = blockIdx.y * 32;   // feature dim
    for (int i = threadIdx.y; i < 32; i += 8)
        tile[i][threadIdx.x] = g_bn[((size_t)b * HALF + j0 + i) * KVD + d0 + threadIdx.x];
    __syncthreads();
    for (int i = threadIdx.y; i < 32; i += 8)
        g_bnT[((size_t)b * KVD + d0 + i) * HALF + j0 + threadIdx.x] = tile[threadIdx.x][i];
}

// ---------------- scores + per-a-row max/argmax (first occurrence) ----------------
// grid (64, B) ; block 256. Each block: 16 a-rows vs all 1024 b-rows.
__global__ void __launch_bounds__(256) score_k()
{
    __shared__ float a_s[16][256];
    __shared__ float rs[256];
    __shared__ int   rj[256];
    int b   = blockIdx.y;
    int a0  = blockIdx.x * 16;
    int tid = threadIdx.x;

    #pragma unroll
    for (int i = 0; i < 4; i++) {
        int s = tid + i * 256;          // 0..1023
        int r = s >> 6;                 // 0..15
        int c4 = s & 63;                // 0..63
        *(float4*)&a_s[r][c4 * 4] =
            *(const float4*)(g_an + ((size_t)b * HALF + a0 + r) * KVD + c4 * 4);
    }
    __syncthreads();

    float bs[16]; int bj[16];
    #pragma unroll
    for (int i = 0; i < 16; i++) { bs[i] = -1e30f; bj[i] = 0; }

    const float* bt = g_bnT + (size_t)b * KVD * HALF;
    for (int jc = 0; jc < 4; jc++) {
        int j = jc * 256 + tid;
        float acc[16];
        #pragma unroll
        for (int i = 0; i < 16; i++) acc[i] = 0.f;
        #pragma unroll 4
        for (int d4 = 0; d4 < 64; d4++) {
            float b0 = bt[(d4 * 4 + 0) * HALF + j];
            float b1 = bt[(d4 * 4 + 1) * HALF + j];
            float b2 = bt[(d4 * 4 + 2) * HALF + j];
            float b3 = bt[(d4 * 4 + 3) * HALF + j];
            #pragma unroll
            for (int i = 0; i < 16; i++) {
                float4 a4 = *(const float4*)&a_s[i][d4 * 4];
                acc[i] += a4.x * b0 + a4.y * b1 + a4.z * b2 + a4.w * b3;
            }
        }
        #pragma unroll
        for (int i = 0; i < 16; i++)
            if (acc[i] > bs[i]) { bs[i] = acc[i]; bj[i] = j; }
    }

    // per-row block reduction with min-index tie-break
    for (int i = 0; i < 16; i++) {
        rs[tid] = bs[i]; rj[tid] = bj[i];
        __syncthreads();
        for (int s = 128; s > 0; s >>= 1) {
            if (tid < s) {
                float s2 = rs[tid + s]; int j2 = rj[tid + s];
                if (s2 > rs[tid] || (s2 == rs[tid] && j2 < rj[tid])) {
                    rs[tid] = s2; rj[tid] = j2;
                }
            }
            __syncthreads();
        }
        if (tid == 0) {
            g_bestS[b * HALF + a0 + i] = rs[0];
            g_bestB[b * HALF + a0 + i] = rj[0];
        }
        __syncthreads();
    }
}

// ---------------- sort + greedy select + keep/partner (1 block per batch) ----------------
__global__ void __launch_bounds__(512) select_k()
{
    __shared__ float key[1024];
    __shared__ int   aid[1024];
    __shared__ int   bb[1024];
    __shared__ unsigned char used[1024];
    __shared__ unsigned char mask[2048];
    __shared__ int ga[256], gb[256];
    __shared__ int keepb[NM];
    int b = blockIdx.x, tid = threadIdx.x;

    for (int i = tid; i < 1024; i += 512) {
        key[i]  = g_bestS[b * HALF + i];
        aid[i]  = i;
        bb[i]   = g_bestB[b * HALF + i];
        used[i] = 0;
    }
    for (int i = tid; i < 2048; i += 512) mask[i] = 1;
    __syncthreads();

    // bitonic sort: descending by key, ties -> smaller index first (== stable argsort(-key))
    for (int k = 2; k <= 1024; k <<= 1) {
        for (int j = k >> 1; j > 0; j >>= 1) {
            int t   = tid;
            int idx = ((t & ~(j - 1)) << 1) | (t & (j - 1));
            int ixj = idx | j;
            bool desc = ((idx & k) == 0);
            float ki = key[idx], kj = key[ixj];
            int   ai = aid[idx], aj = aid[ixj];
            bool ibetter = (ki > kj) || (ki == kj && ai < aj);
            bool dos = desc ? !ibetter : ibetter;
            if (dos) { key[idx] = kj; key[ixj] = ki; aid[idx] = aj; aid[ixj] = ai; }
            __syncthreads();
        }
    }

    if (tid == 0) {
        int cnt = 0;
        for (int t = 0; t < 1024 && cnt < RR; t++) {
            int a  = aid[t];
            int bl = bb[a];
            if (!used[bl]) {
                used[bl] = 1;
                ga[cnt] = 2 * a;
                gb[cnt] = 2 * bl + 1;
                cnt++;
            }
        }
        if (cnt == 0) { ga[0] = 0; gb[0] = 1; cnt = 1; }
        for (int t = cnt; t < RR; t++) { ga[t] = ga[0]; gb[t] = gb[0]; }
        for (int t = 0; t < RR; t++) mask[gb[t]] = 0;
        int c2 = 0;
        for (int p = 0; p < NN && c2 < NM; p++)
            if (mask[p]) keepb[c2++] = p;
    }
    __syncthreads();

    for (int i = tid; i < NN; i += 512) g_partner[b * NN + i] = -1;
    for (int i = tid; i < NM; i += 512) g_keep[b * NM + i] = keepb[i];
    if (tid < RR) { g_ga[b * RR + tid] = ga[tid]; g_gb[b * RR + tid] = gb[tid]; }
    __syncthreads();
    if (tid < RR) g_partner[b * NN + ga[tid]] = gb[tid];
}

// ---------------- merge: build x_m ----------------
__global__ void merge_k(const float* __restrict__ x)
{
    int row = blockIdx.x;                 // 0..3583
    int b = row / NM, m = row % NM;
    int p  = g_keep[b * NM + m];
    int pr = g_partner[b * NN + p];
    const float4* xs = (const float4*)(x + (size_t)(b * NN + p) * DM);
    float4* dst = (float4*)(g_xm + (size_t)row * DM);
    int t = threadIdx.x;                  // 256 threads, 256 float4 = 1024 floats
    if (pr < 0) {
        dst[t] = xs[t];
    } else {
        const float4* xb2 = (const float4*)(x + (size_t)(b * NN + pr) * DM);
        float4 u = xs[t], w = xb2[t];
        dst[t] = make_float4((u.x + w.x) * 0.5f, (u.y + w.y) * 0.5f,
                             (u.z + w.z) * 0.5f, (u.w + w.w) * 0.5f);
    }
}

// ---------------- RoPE ----------------
__global__ void rope_q_k(const float* __restrict__ fr)
{
    int row = blockIdx.x;                 // 0..3583
    int m = row % NM;
    int t = threadIdx.x;                  // 512: h = t/32, pair j = t%32
    int jp = t & 31;
    float c = fr[m * 64 + 2 * jp];
    float s = fr[m * 64 + 2 * jp + 1];
    float2* q = (float2*)(g_q + (size_t)row * DM);
    float2 v = q[t];
    q[t] = make_float2(v.x * c - v.y * s, v.x * s + v.y * c);
}

__global__ void rope_k_k(const float* __restrict__ fr)
{
    int row = blockIdx.x;
    int m = row % NM;
    int t = threadIdx.x;                  // 128
    int jp = t & 31;
    float c = fr[m * 64 + 2 * jp];
    float s = fr[m * 64 + 2 * jp + 1];
    float2* k = (float2*)(g_kb + (size_t)row * KVD);
    float2 v = k[t];
    k[t] = make_float2(v.x * c - v.y * s, v.x * s + v.y * c);
}

// ---------------- flash attention (64q x 64k tiles, d=64) ----------------
#define FST 68
__global__ void __launch_bounds__(256) flash_k()
{
    extern __shared__ float sm[];
    float* Qs = sm;                 // [64 d][68]  (transposed: Qs[d][qrow])
    float* Ks = sm + 64 * FST;      // [64 d][68]  (transposed: Ks[d][kcol])
    float* Vs = sm + 2 * 64 * FST;  // [64 k][68]  (natural: Vs[k][dim])
    float* Ps = sm + 3 * 64 * FST;  // [64 q][68]  (natural)

    int bh = blockIdx.y;
    int b = bh >> 4, h = bh & 15, kh = h >> 2;
    int q0 = blockIdx.x * 64;
    int tid = threadIdx.x;
    int tx = tid & 15, ty = tid >> 4;

    // load Q tile transposed
    const float* Qg = g_q + (size_t)(b * NM + q0) * DM + h * HD;
    #pragma unroll
    for (int i = 0; i < 4; i++) {
        int s = tid + i * 256;        // 0..1023
        int r = s >> 4;               // 0..63 (q row)
        int c4 = s & 15;              // 0..15 (dim/4)
        float4 v = *(const float4*)(Qg + (size_t)r * DM + c4 * 4);
        Qs[(c4 * 4 + 0) * FST + r] = v.x;
        Qs[(c4 * 4 + 1) * FST + r] = v.y;
        Qs[(c4 * 4 + 2) * FST + r] = v.z;
        Qs[(c4 * 4 + 3) * FST + r] = v.w;
    }

    float m_i[4], l_i[4], O[4][4];
    #pragma unroll
    for (int a = 0; a < 4; a++) {
        m_i[a] = -1e30f; l_i[a] = 0.f;
        #pragma unroll
        for (int c = 0; c < 4; c++) O[a][c] = 0.f;
    }

    for (int kt = 0; kt < NM / 64; kt++) {
        __syncthreads();
        const float* Kg = g_kb + (size_t)(b * NM + kt * 64) * KVD + kh * HD;
        const float* Vg = g_v  + (size_t)(b * NM + kt * 64) * KVD + kh * HD;
        #pragma unroll
        for (int i = 0; i < 4; i++) {
            int s = tid + i * 256;
            int r = s >> 4, c4 = s & 15;
            float4 kv = *(const float4*)(Kg + (size_t)r * KVD + c4 * 4);
            Ks[(c4 * 4 + 0) * FST + r] = kv.x;
            Ks[(c4 * 4 + 1) * FST + r] = kv.y;
            Ks[(c4 * 4 + 2) * FST + r] = kv.z;
            Ks[(c4 * 4 + 3) * FST + r] = kv.w;
            *(float4*)&Vs[r * FST + c4 * 4] = *(const float4*)(Vg + (size_t)r * KVD + c4 * 4);
        }
        __syncthreads();

        // S = Q K^T  (outer product over d)
        float S[4][4];
        #pragma unroll
        for (int a = 0; a < 4; a++)
            #pragma unroll
            for (int c = 0; c < 4; c++) S[a][c] = 0.f;
        #pragma unroll 8
        for (int d = 0; d < 64; d++) {
            float4 qv = *(const float4*)&Qs[d * FST + ty * 4];
            float4 kv = *(const float4*)&Ks[d * FST + tx * 4];
            S[0][0] += qv.x * kv.x; S[0][1] += qv.x * kv.y; S[0][2] += qv.x * kv.z; S[0][3] += qv.x * kv.w;
            S[1][0] += qv.y * kv.x; S[1][1] += qv.y * kv.y; S[1][2] += qv.y * kv.z; S[1][3] += qv.y * kv.w;
            S[2][0] += qv.z * kv.x; S[2][1] += qv.z * kv.y; S[2][2] += qv.z * kv.z; S[2][3] += qv.z * kv.w;
            S[3][0] += qv.w * kv.x; S[3][1] += qv.w * kv.y; S[3][2] += qv.w * kv.z; S[3][3] += qv.w * kv.w;
        }

        // online softmax
        #pragma unroll
        for (int a = 0; a < 4; a++) {
            #pragma unroll
            for (int c = 0; c < 4; c++) S[a][c] *= 0.125f;
            float mx = fmaxf(fmaxf(S[a][0], S[a][1]), fmaxf(S[a][2], S[a][3]));
            #pragma unroll
            for (int o = 1; o <= 8; o <<= 1)
                mx = fmaxf(mx, __shfl_xor_sync(0xffffffffu, mx, o));
            float mn = fmaxf(m_i[a], mx);
            float corr = __expf(m_i[a] - mn);
            float rsum = 0.f;
            #pragma unroll
            for (int c = 0; c < 4; c++) {
                float p = __expf(S[a][c] - mn);
                S[a][c] = p; rsum += p;
            }
            #pragma unroll
            for (int o = 1; o <= 8; o <<= 1)
                rsum += __shfl_xor_sync(0xffffffffu, rsum, o);
            l_i[a] = l_i[a] * corr + rsum;
            m_i[a] = mn;
            #pragma unroll
            for (int c = 0; c < 4; c++) O[a][c] *= corr;
            *(float4*)&Ps[(ty * 4 + a) * FST + tx * 4] =
                make_float4(S[a][0], S[a][1], S[a][2], S[a][3]);
        }
        __syncthreads();

        // O += P V
        #pragma unroll 4
        for (int k4 = 0; k4 < 16; k4++) {
            float4 pv[4], vv[4];
            #pragma unroll
            for (int a = 0; a < 4; a++)
                pv[a] = *(const float4*)&Ps[(ty * 4 + a) * FST + k4 * 4];
            #pragma unroll
            for (int e = 0; e < 4; e++)
                vv[e] = *(const float4*)&Vs[(k4 * 4 + e) * FST + tx * 4];
            #pragma unroll
            for (int a = 0; a < 4; a++) {
                O[a][0] += pv[a].x * vv[0].x + pv[a].y * vv[1].x + pv[a].z * vv[2].x + pv[a].w * vv[3].x;
                O[a][1] += pv[a].x * vv[0].y + pv[a].y * vv[1].y + pv[a].z * vv[2].y + pv[a].w * vv[3].y;
                O[a][2] += pv[a].x * vv[0].z + pv[a].y * vv[1].z + pv[a].z * vv[2].z + pv[a].w * vv[3].z;
                O[a][3] += pv[a].x * vv[0].w + pv[a].y * vv[1].w + pv[a].z * vv[2].w + pv[a].w * vv[3].w;
            }
        }
    }

    #pragma unroll
    for (int a = 0; a < 4; a++) {
        float inv = 1.f / l_i[a];
        *(float4*)(g_o + (size_t)(b * NM + q0 + ty * 4 + a) * DM + h * HD + tx * 4) =
            make_float4(O[a][0] * inv, O[a][1] * inv, O[a][2] * inv, O[a][3] * inv);
    }
}

// ---------------- unmerge ----------------
__global__ void zero_k(float4* o)
{
    o[(size_t)blockIdx.x * 256 + threadIdx.x] = make_float4(0.f, 0.f, 0.f, 0.f);
}

__global__ void scatter_k(float* __restrict__ out)
{
    int row = blockIdx.x;
    int b = row / NM, m = row % NM;
    int p = g_keep[b * NM + m];
    float4* dst = (float4*)(out + (size_t)(b * NN + p) * DM);
    const float4* src = (const float4*)(g_om + (size_t)row * DM);
    dst[threadIdx.x] = src[threadIdx.x];
}

__global__ void copygab_k(float* __restrict__ out)
{
    int i = blockIdx.x;                   // 0..511
    int b = i / RR, t = i % RR;
    int a = g_ga[b * RR + t];
    int g = g_gb[b * RR + t];
    const float4* src = (const float4*)(out + (size_t)(b * NN + a) * DM);
    float4*       dst = (float4*)(out + (size_t)(b * NN + g) * DM);
    dst[threadIdx.x] = src[threadIdx.x];
}

// ---------------- launcher ----------------
extern "C" void kernel_launch(void* const* d_in, const int* in_sizes, int n_in,
                              void* d_out, int out_size)
{
    const float* x  = (const float*)d_in[0];
    const float* fr = (const float*)d_in[1];
    const float* Wq = (const float*)d_in[2];
    const float* Wk = (const float*)d_in[3];
    const float* Wv = (const float*)d_in[4];
    const float* Wo = (const float*)d_in[5];
    float* out = (float*)d_out;

    float *p_metric, *p_xm, *p_q, *p_kb, *p_v, *p_o, *p_om;
    cudaGetSymbolAddress((void**)&p_metric, g_metric);
    cudaGetSymbolAddress((void**)&p_xm,     g_xm);
    cudaGetSymbolAddress((void**)&p_q,      g_q);
    cudaGetSymbolAddress((void**)&p_kb,     g_kb);
    cudaGetSymbolAddress((void**)&p_v,      g_v);
    cudaGetSymbolAddress((void**)&p_o,      g_o);
    cudaGetSymbolAddress((void**)&p_om,     g_om);

    const int FLASH_SMEM = 4 * 64 * FST * sizeof(float);   // 69632
    cudaFuncSetAttribute(flash_k, cudaFuncAttributeMaxDynamicSharedMemorySize, FLASH_SMEM);

    // 1. metric = x @ Wk   (4096 x 256 x 1024)
    gemm_k<<<dim3(KVD / 128, BB * NN / 128), 256>>>(x, Wk, p_metric, BB * NN, KVD, DM);
    // 2. normalize + split even/odd
    normalize_k<<<BB * NN, 256>>>();
    // 3. transpose bn
    transpose_k<<<dim3(HALF / 32, KVD / 32, BB), dim3(32, 8)>>>();
    // 4. scores + argmax
    score_k<<<dim3(HALF / 16, BB), 256>>>();
    // 5. sort + greedy + keep/partner
    select_k<<<BB, 512>>>();
    // 6. merge
    merge_k<<<MROWS, 256>>>(x);
    // 7-9. projections
    gemm_k<<<dim3(DM / 128,  MROWS / 128), 256>>>(p_xm, Wq, p_q,  MROWS, DM,  DM);
    gemm_k<<<dim3(KVD / 128, MROWS / 128), 256>>>(p_xm, Wk, p_kb, MROWS, KVD, DM);
    gemm_k<<<dim3(KVD / 128, MROWS / 128), 256>>>(p_xm, Wv, p_v,  MROWS, KVD, DM);
    // 10-11. rope
    rope_q_k<<<MROWS, 512>>>(fr);
    rope_k_k<<<MROWS, 128>>>(fr);
    // 12. attention
    flash_k<<<dim3(NM / 64, BB * NH), 256, FLASH_SMEM>>>();
    // 13. output projection
    gemm_k<<<dim3(DM / 128, MROWS / 128), 256>>>(p_o, Wo, p_om, MROWS, DM, DM);
    // 14-16. unmerge
    zero_k<<<(BB * NN * DM) / 1024, 256>>>((float4*)out);
    scatter_k<<<MROWS, 256>>>(out);
    copygab_k<<<BB * RR, 256>>>(out);
    (void)in_sizes; (void)n_in; (void)out_size;
}

// round 11
// speedup vs baseline: 1.9312x; 1.9312x over previous
#include <cuda_runtime.h>
#include <cuda_bf16.h>
#include <math.h>
#include <stdint.h>

// ---------------- problem constants ----------------
#define BB    2
#define NN    2048
#define DM    1024
#define NH    16
#define NKV   4
#define HD    64
#define RR    256
#define NM    1792          // N - R
#define HALF  1024          // N/2
#define MROWS (BB*NM)       // 3584
#define KVD   (NKV*HD)      // 256

// ---------------- scratch (static device memory) ----------------
__device__ float g_metric[BB*NN*KVD];
__device__ float g_an [BB*HALF*KVD];
__device__ float g_bn [BB*HALF*KVD];
__device__ float g_bnT[BB*KVD*HALF];
__device__ float g_pS[BB*4*HALF];
__device__ int   g_pB[BB*4*HALF];
__device__ float g_bestS[BB*HALF];
__device__ int   g_bestB[BB*HALF];
__device__ int   g_ga[BB*RR];
__device__ int   g_gb[BB*RR];
__device__ int   g_partner[BB*NN];
__device__ int   g_keep[BB*NM];
__device__ float g_xm[(size_t)MROWS*DM];
__device__ float g_q [(size_t)MROWS*DM];
__device__ float g_kb[(size_t)MROWS*KVD];
__device__ float g_v [(size_t)MROWS*KVD];
__device__ float g_o [(size_t)MROWS*DM];
__device__ float g_om[(size_t)MROWS*DM];
// split-bf16 operands for tensor-core GEMMs
__device__ __nv_bfloat16 g_xm_h[(size_t)MROWS*DM], g_xm_l[(size_t)MROWS*DM];
__device__ __nv_bfloat16 g_o_h [(size_t)MROWS*DM], g_o_l [(size_t)MROWS*DM];
__device__ __nv_bfloat16 g_WqT_h[DM*DM],  g_WqT_l[DM*DM];
__device__ __nv_bfloat16 g_WkT_h[KVD*DM], g_WkT_l[KVD*DM];
__device__ __nv_bfloat16 g_WvT_h[KVD*DM], g_WvT_l[KVD*DM];
__device__ __nv_bfloat16 g_WoT_h[DM*DM],  g_WoT_l[DM*DM];

// ================= warp-MMA helpers (sm_80+ ISA, valid on plain sm_103) =====
__device__ __forceinline__ uint32_t smem_u32(const void* p) {
    uint32_t a;
    asm("{ .reg .u64 t; cvta.to.shared.u64 t, %1; cvt.u32.u64 %0, t; }" : "=r"(a) : "l"(p));
    return a;
}
__device__ __forceinline__ void ldsm_x4(uint32_t* r, uint32_t a) {
    asm volatile("ldmatrix.sync.aligned.m8n8.x4.shared.b16 {%0,%1,%2,%3}, [%4];"
                 : "=r"(r[0]), "=r"(r[1]), "=r"(r[2]), "=r"(r[3]) : "r"(a));
}
__device__ __forceinline__ void ldsm_x2(uint32_t* r, uint32_t a) {
    asm volatile("ldmatrix.sync.aligned.m8n8.x2.shared.b16 {%0,%1}, [%2];"
                 : "=r"(r[0]), "=r"(r[1]) : "r"(a));
}
__device__ __forceinline__ void mma16816(float* c, const uint32_t* a, const uint32_t* b) {
    asm volatile(
        "mma.sync.aligned.m16n8k16.row.col.f32.bf16.bf16.f32 "
        "{%0,%1,%2,%3}, {%4,%5,%6,%7}, {%8,%9}, {%0,%1,%2,%3};"
        : "+f"(c[0]), "+f"(c[1]), "+f"(c[2]), "+f"(c[3])
        : "r"(a[0]), "r"(a[1]), "r"(a[2]), "r"(a[3]), "r"(b[0]), "r"(b[1]));
}

// ================= split-bf16 HMMA GEMM =================
// C[M,N] = A[M,K] @ W, with B = W^T supplied as [N,K] bf16 hi/lo (K-major).
// D += Ah*Bh + Ah*Bl + Al*Bh  in fp32 accumulators. CTA tile 128x128, warp 64x32.
#define BKC 32
#define LDT 40   // padded row stride (bf16): conflict-free ldmatrix phases
__global__ void __launch_bounds__(256) hmma_gemm(
    const __nv_bfloat16* __restrict__ Ah, const __nv_bfloat16* __restrict__ Al,
    const __nv_bfloat16* __restrict__ Bh, const __nv_bfloat16* __restrict__ Bl,
    float* __restrict__ C, int M, int N, int K)
{
    __shared__ __nv_bfloat16 As_h[128][LDT], As_l[128][LDT];
    __shared__ __nv_bfloat16 Bs_h[128][LDT], Bs_l[128][LDT];
    const int tid = threadIdx.x, lane = tid & 31, wid = tid >> 5;
    const int wm = (wid & 1) * 64;      // warp m-offset within CTA
    const int wn = (wid >> 1) * 32;     // warp n-offset
    const int m0 = blockIdx.y * 128, n0 = blockIdx.x * 128;

    float acc[4][4][4];
    #pragma unroll
    for (int i = 0; i < 4; i++)
        #pragma unroll
        for (int j = 0; j < 4; j++)
            #pragma unroll
            for (int q = 0; q < 4; q++) acc[i][j][q] = 0.f;

    for (int kc = 0; kc < K; kc += BKC) {
        #pragma unroll
        for (int i = 0; i < 2; i++) {
            int s = tid + i * 256;          // 0..511
            int r = s >> 2;                 // 0..127
            int u = (s & 3) * 8;            // 0,8,16,24
            *(uint4*)&As_h[r][u] = *(const uint4*)(Ah + (size_t)(m0 + r) * K + kc + u);
            *(uint4*)&As_l[r][u] = *(const uint4*)(Al + (size_t)(m0 + r) * K + kc + u);
            *(uint4*)&Bs_h[r][u] = *(const uint4*)(Bh + (size_t)(n0 + r) * K + kc + u);
            *(uint4*)&Bs_l[r][u] = *(const uint4*)(Bl + (size_t)(n0 + r) * K + kc + u);
        }
        __syncthreads();
        #pragma unroll
        for (int ks = 0; ks < 2; ks++) {
            uint32_t bh[4][2], bl[4][2];
            #pragma unroll
            for (int nt = 0; nt < 4; nt++) {
                int nrow = wn + nt * 8 + (lane & 7);
                int kcol = ks * 16 + ((lane >> 3) & 1) * 8;
                ldsm_x2(bh[nt], smem_u32(&Bs_h[nrow][kcol]));
                ldsm_x2(bl[nt], smem_u32(&Bs_l[nrow][kcol]));
            }
            #pragma unroll
            for (int mt = 0; mt < 4; mt++) {
                int arow = wm + mt * 16 + (lane & 15);
                int acol = ks * 16 + (lane >> 4) * 8;
                uint32_t ah[4], al[4];
                ldsm_x4(ah, smem_u32(&As_h[arow][acol]));
                ldsm_x4(al, smem_u32(&As_l[arow][acol]));
                #pragma unroll
                for (int nt = 0; nt < 4; nt++) {
                    mma16816(acc[mt][nt], ah, bh[nt]);
                    mma16816(acc[mt][nt], ah, bl[nt]);
                    mma16816(acc[mt][nt], al, bh[nt]);
                }
            }
        }
        __syncthreads();
    }
    #pragma unroll
    for (int mt = 0; mt < 4; mt++) {
        #pragma unroll
        for (int nt = 0; nt < 4; nt++) {
            int row = m0 + wm + mt * 16 + (lane >> 2);
            int col = n0 + wn + nt * 8 + (lane & 3) * 2;
            *(float2*)(C + (size_t)row * N + col)       = make_float2(acc[mt][nt][0], acc[mt][nt][1]);
            *(float2*)(C + (size_t)(row + 8) * N + col) = make_float2(acc[mt][nt][2], acc[mt][nt][3]);
        }
    }
}

// ---------------- split fp32 -> (hi, lo) bf16 ----------------
__global__ void split_k(const float4* __restrict__ in,
                        __nv_bfloat16* __restrict__ hi, __nv_bfloat16* __restrict__ lo, int n4)
{
    int i = blockIdx.x * 256 + threadIdx.x;
    if (i >= n4) return;
    float4 v = in[i];
    __nv_bfloat16 h0 = __float2bfloat16(v.x), h1 = __float2bfloat16(v.y);
    __nv_bfloat16 h2 = __float2bfloat16(v.z), h3 = __float2bfloat16(v.w);
    __nv_bfloat16 l0 = __float2bfloat16(v.x - __bfloat162float(h0));
    __nv_bfloat16 l1 = __float2bfloat16(v.y - __bfloat162float(h1));
    __nv_bfloat16 l2 = __float2bfloat16(v.z - __bfloat162float(h2));
    __nv_bfloat16 l3 = __float2bfloat16(v.w - __bfloat162float(h3));
    __nv_bfloat162* H = (__nv_bfloat162*)hi;
    __nv_bfloat162* L = (__nv_bfloat162*)lo;
    H[2*i]   = __halves2bfloat162(h0, h1);
    H[2*i+1] = __halves2bfloat162(h2, h3);
    L[2*i]   = __halves2bfloat162(l0, l1);
    L[2*i+1] = __halves2bfloat162(l2, l3);
}

// ---------------- transpose + split: W[K][N] -> WT_hi/lo[N][K] ----------------
__global__ void splitT_k(const float* __restrict__ W,
                         __nv_bfloat16* __restrict__ Th, __nv_bfloat16* __restrict__ Tl,
                         int K, int N)
{
    __shared__ float t[32][33];
    int k0 = blockIdx.y * 32, n0 = blockIdx.x * 32;
    int tx = threadIdx.x, ty = threadIdx.y;
    for (int i = ty; i < 32; i += 8)
        t[i][tx] = W[(size_t)(k0 + i) * N + n0 + tx];
    __syncthreads();
    for (int i = ty; i < 32; i += 8) {
        float v = t[tx][i];                        // = W[k0+tx][n0+i]
        __nv_bfloat16 h = __float2bfloat16(v);
        size_t o = (size_t)(n0 + i) * K + k0 + tx;
        Th[o] = h;
        Tl[o] = __float2bfloat16(v - __bfloat162float(h));
    }
}

// ---------------- generic fp32 SGEMM (selection path only — bit-exact) ------
__global__ void __launch_bounds__(256)
gemm_k(const float* __restrict__ A, const float* __restrict__ B,
       float* __restrict__ C, int M, int N, int K)
{
    const int BK = 16;
    __shared__ float As[16][132];
    __shared__ float Bs[16][132];
    const int tid = threadIdx.x;
    const int tx  = tid & 15;
    const int ty  = tid >> 4;
    const int m0  = blockIdx.y * 128;
    const int n0  = blockIdx.x * 128;

    float acc[8][8];
    #pragma unroll
    for (int i = 0; i < 8; i++)
        #pragma unroll
        for (int j = 0; j < 8; j++) acc[i][j] = 0.f;

    for (int k0 = 0; k0 < K; k0 += BK) {
        #pragma unroll
        for (int i = 0; i < 2; i++) {
            int s  = tid + i * 256;
            int r  = s >> 2;
            int kc = (s & 3) * 4;
            float4 v = *(const float4*)(A + (size_t)(m0 + r) * K + k0 + kc);
            As[kc + 0][r] = v.x; As[kc + 1][r] = v.y;
            As[kc + 2][r] = v.z; As[kc + 3][r] = v.w;
        }
        #pragma unroll
        for (int i = 0; i < 2; i++) {
            int s = tid + i * 256;
            int r = s >> 5;
            int c = (s & 31) * 4;
            *(float4*)&Bs[r][c] = *(const float4*)(B + (size_t)(k0 + r) * N + n0 + c);
        }
        __syncthreads();
        #pragma unroll
        for (int kk = 0; kk < BK; kk++) {
            float ra[8], rb[8];
            *(float4*)&ra[0] = *(const float4*)&As[kk][ty * 8];
            *(float4*)&ra[4] = *(const float4*)&As[kk][ty * 8 + 4];
            *(float4*)&rb[0] = *(const float4*)&Bs[kk][tx * 8];
            *(float4*)&rb[4] = *(const float4*)&Bs[kk][tx * 8 + 4];
            #pragma unroll
            for (int i = 0; i < 8; i++)
                #pragma unroll
                for (int j = 0; j < 8; j++) acc[i][j] += ra[i] * rb[j];
        }
        __syncthreads();
    }
    #pragma unroll
    for (int i = 0; i < 8; i++) {
        size_t cr = (size_t)(m0 + ty * 8 + i) * N + n0 + tx * 8;
        *(float4*)(C + cr)     = make_float4(acc[i][0], acc[i][1], acc[i][2], acc[i][3]);
        *(float4*)(C + cr + 4) = make_float4(acc[i][4], acc[i][5], acc[i][6], acc[i][7]);
    }
}

// ---------------- normalize metric rows into an (even) / bn (odd) ----------------
__global__ void normalize_k()
{
    __shared__ float wsum[8];
    __shared__ float total;
    int row = blockIdx.x, t = threadIdx.x;
    float v = g_metric[(size_t)row * KVD + t];
    float ss = v * v;
    #pragma unroll
    for (int o = 16; o; o >>= 1) ss += __shfl_xor_sync(0xffffffffu, ss, o);
    if ((t & 31) == 0) wsum[t >> 5] = ss;
    __syncthreads();
    if (t == 0) {
        float s2 = 0.f;
        #pragma unroll
        for (int i = 0; i < 8; i++) s2 += wsum[i];
        total = fmaxf(sqrtf(s2), 1e-12f);
    }
    __syncthreads();
    float outv = v / total;
    int b = row >> 11, i = row & 2047;
    if (i & 1) g_bn[((size_t)b * HALF + (i >> 1)) * KVD + t] = outv;
    else       g_an[((size_t)b * HALF + (i >> 1)) * KVD + t] = outv;
}

// ---------------- transpose bn (1024x256) -> bnT (256x1024) per batch ----------------
__global__ void transpose_k()
{
    __shared__ float tile[32][33];
    int b  = blockIdx.z;
    int j0 = blockIdx.x * 32;
    int d0 = blockIdx.y * 32;
    for (int i = threadIdx.y; i < 32; i += 8)
        tile[i][threadIdx.x] = g_bn[((size_t)b * HALF + j0 + i) * KVD + d0 + threadIdx.x];
    __syncthreads();
    for (int i = threadIdx.y; i < 32; i += 8)
        g_bnT[((size_t)b * KVD + d0 + i) * HALF + j0 + threadIdx.x] = tile[threadIdx.x][i];
}

// ---------------- scores + per-a-row partial argmax, j-chunked (bit-exact) ---
__global__ void __launch_bounds__(256) score_k()
{
    __shared__ float a_s[16][256];
    __shared__ float rs[256];
    __shared__ int   rj[256];
    int b   = blockIdx.z;
    int jc  = blockIdx.y;
    int a0  = blockIdx.x * 16;
    int tid = threadIdx.x;

    #pragma unroll
    for (int i = 0; i < 4; i++) {
        int s = tid + i * 256;
        int r = s >> 6;
        int c4 = s & 63;
        *(float4*)&a_s[r][c4 * 4] =
            *(const float4*)(g_an + ((size_t)b * HALF + a0 + r) * KVD + c4 * 4);
    }
    __syncthreads();

    const float* bt = g_bnT + (size_t)b * KVD * HALF;
    int j = jc * 256 + tid;
    float acc[16];
    #pragma unroll
    for (int i = 0; i < 16; i++) acc[i] = 0.f;
    #pragma unroll 4
    for (int d4 = 0; d4 < 64; d4++) {
        float b0 = bt[(d4 * 4 + 0) * HALF + j];
        float b1 = bt[(d4 * 4 + 1) * HALF + j];
        float b2 = bt[(d4 * 4 + 2) * HALF + j];
        float b3 = bt[(d4 * 4 + 3) * HALF + j];
        #pragma unroll
        for (int i = 0; i < 16; i++) {
            float4 a4 = *(const float4*)&a_s[i][d4 * 4];
            acc[i] += a4.x * b0 + a4.y * b1 + a4.z * b2 + a4.w * b3;
        }
    }

    for (int i = 0; i < 16; i++) {
        rs[tid] = acc[i]; rj[tid] = j;
        __syncthreads();
        for (int s = 128; s > 0; s >>= 1) {
            if (tid < s) {
                float s2 = rs[tid + s]; int j2 = rj[tid + s];
                if (s2 > rs[tid] || (s2 == rs[tid] && j2 < rj[tid])) {
                    rs[tid] = s2; rj[tid] = j2;
                }
            }
            __syncthreads();
        }
        if (tid == 0) {
            g_pS[(b * 4 + jc) * HALF + a0 + i] = rs[0];
            g_pB[(b * 4 + jc) * HALF + a0 + i] = rj[0];
        }
        __syncthreads();
    }
}

// ---------------- reduce chunk partials -> bestS/bestB (first occurrence) ----
__global__ void argred_k()
{
    int b = blockIdx.y;
    int a = blockIdx.x * 256 + threadIdx.x;
    float bs = -1e30f; int bj = 0;
    #pragma unroll
    for (int c = 0; c < 4; c++) {
        float s = g_pS[(b * 4 + c) * HALF + a];
        int   j = g_pB[(b * 4 + c) * HALF + a];
        if (s > bs) { bs = s; bj = j; }   // chunks ascending in j -> first occurrence
    }
    g_bestS[b * HALF + a] = bs;
    g_bestB[b * HALF + a] = bj;
}

// ---------------- sort + greedy select + keep/partner (1 block per batch) ----
__global__ void __launch_bounds__(512) select_k()
{
    __shared__ float key[1024];
    __shared__ int   aid[1024];
    __shared__ int   bb[1024];
    __shared__ unsigned char used[1024];
    __shared__ unsigned char mask[2048];
    __shared__ int ga[256], gb[256];
    __shared__ int keepb[NM];
    int b = blockIdx.x, tid = threadIdx.x;

    for (int i = tid; i < 1024; i += 512) {
        key[i]  = g_bestS[b * HALF + i];
        aid[i]  = i;
        bb[i]   = g_bestB[b * HALF + i];
        used[i] = 0;
    }
    for (int i = tid; i < 2048; i += 512) mask[i] = 1;
    __syncthreads();

    for (int k = 2; k <= 1024; k <<= 1) {
        for (int j = k >> 1; j > 0; j >>= 1) {
            int t   = tid;
            int idx = ((t & ~(j - 1)) << 1) | (t & (j - 1));
            int ixj = idx | j;
            bool desc = ((idx & k) == 0);
            float ki = key[idx], kj = key[ixj];
            int   ai = aid[idx], aj = aid[ixj];
            bool ibetter = (ki > kj) || (ki == kj && ai < aj);
            bool dos = desc ? !ibetter : ibetter;
            if (dos) { key[idx] = kj; key[ixj] = ki; aid[idx] = aj; aid[ixj] = ai; }
            __syncthreads();
        }
    }

    if (tid == 0) {
        int cnt = 0;
        for (int t = 0; t < 1024 && cnt < RR; t++) {
            int a  = aid[t];
            int bl = bb[a];
            if (!used[bl]) {
                used[bl] = 1;
                ga[cnt] = 2 * a;
                gb[cnt] = 2 * bl + 1;
                cnt++;
            }
        }
        if (cnt == 0) { ga[0] = 0; gb[0] = 1; cnt = 1; }
        for (int t = cnt; t < RR; t++) { ga[t] = ga[0]; gb[t] = gb[0]; }
        for (int t = 0; t < RR; t++) mask[gb[t]] = 0;
        int c2 = 0;
        for (int p = 0; p < NN && c2 < NM; p++)
            if (mask[p]) keepb[c2++] = p;
    }
    __syncthreads();

    for (int i = tid; i < NN; i += 512) g_partner[b * NN + i] = -1;
    for (int i = tid; i < NM; i += 512) g_keep[b * NM + i] = keepb[i];
    if (tid < RR) { g_ga[b * RR + tid] = ga[tid]; g_gb[b * RR + tid] = gb[tid]; }
    __syncthreads();
    if (tid < RR) g_partner[b * NN + ga[tid]] = gb[tid];
}

// ---------------- merge: build x_m ----------------
__global__ void merge_k(const float* __restrict__ x)
{
    int row = blockIdx.x;
    int b = row / NM, m = row % NM;
    int p  = g_keep[b * NM + m];
    int pr = g_partner[b * NN + p];
    const float4* xs = (const float4*)(x + (size_t)(b * NN + p) * DM);
    float4* dst = (float4*)(g_xm + (size_t)row * DM);
    int t = threadIdx.x;
    if (pr < 0) {
        dst[t] = xs[t];
    } else {
        const float4* xb2 = (const float4*)(x + (size_t)(b * NN + pr) * DM);
        float4 u = xs[t], w = xb2[t];
        dst[t] = make_float4((u.x + w.x) * 0.5f, (u.y + w.y) * 0.5f,
                             (u.z + w.z) * 0.5f, (u.w + w.w) * 0.5f);
    }
}

// ---------------- RoPE ----------------
__global__ void rope_q_k(const float* __restrict__ fr)
{
    int row = blockIdx.x;
    int m = row % NM;
    int t = threadIdx.x;
    int jp = t & 31;
    float c = fr[m * 64 + 2 * jp];
    float s = fr[m * 64 + 2 * jp + 1];
    float2* q = (float2*)(g_q + (size_t)row * DM);
    float2 v = q[t];
    q[t] = make_float2(v.x * c - v.y * s, v.x * s + v.y * c);
}

__global__ void rope_k_k(const float* __restrict__ fr)
{
    int row = blockIdx.x;
    int m = row % NM;
    int t = threadIdx.x;
    int jp = t & 31;
    float c = fr[m * 64 + 2 * jp];
    float s = fr[m * 64 + 2 * jp + 1];
    float2* k = (float2*)(g_kb + (size_t)row * KVD);
    float2 v = k[t];
    k[t] = make_float2(v.x * c - v.y * s, v.x * s + v.y * c);
}

// ---------------- flash attention (64q x 64k tiles, d=64) ----------------
#define FST 68
__global__ void __launch_bounds__(256) flash_k()
{
    extern __shared__ float smf[];
    float* Qs = smf;
    float* Ks = smf + 64 * FST;
    float* Vs = smf + 2 * 64 * FST;
    float* Ps = smf + 3 * 64 * FST;

    int bh = blockIdx.y;
    int b = bh >> 4, h = bh & 15, kh = h >> 2;
    int q0 = blockIdx.x * 64;
    int tid = threadIdx.x;
    int tx = tid & 15, ty = tid >> 4;

    const float* Qg = g_q + (size_t)(b * NM + q0) * DM + h * HD;
    #pragma unroll
    for (int i = 0; i < 4; i++) {
        int s = tid + i * 256;
        int r = s >> 4;
        int c4 = s & 15;
        float4 v = *(const float4*)(Qg + (size_t)r * DM + c4 * 4);
        Qs[(c4 * 4 + 0) * FST + r] = v.x;
        Qs[(c4 * 4 + 1) * FST + r] = v.y;
        Qs[(c4 * 4 + 2) * FST + r] = v.z;
        Qs[(c4 * 4 + 3) * FST + r] = v.w;
    }

    float m_i[4], l_i[4], O[4][4];
    #pragma unroll
    for (int a = 0; a < 4; a++) {
        m_i[a] = -1e30f; l_i[a] = 0.f;
        #pragma unroll
        for (int c = 0; c < 4; c++) O[a][c] = 0.f;
    }

    for (int kt = 0; kt < NM / 64; kt++) {
        __syncthreads();
        const float* Kg = g_kb + (size_t)(b * NM + kt * 64) * KVD + kh * HD;
        const float* Vg = g_v  + (size_t)(b * NM + kt * 64) * KVD + kh * HD;
        #pragma unroll
        for (int i = 0; i < 4; i++) {
            int s = tid + i * 256;
            int r = s >> 4, c4 = s & 15;
            float4 kv = *(const float4*)(Kg + (size_t)r * KVD + c4 * 4);
            Ks[(c4 * 4 + 0) * FST + r] = kv.x;
            Ks[(c4 * 4 + 1) * FST + r] = kv.y;
            Ks[(c4 * 4 + 2) * FST + r] = kv.z;
            Ks[(c4 * 4 + 3) * FST + r] = kv.w;
            *(float4*)&Vs[r * FST + c4 * 4] = *(const float4*)(Vg + (size_t)r * KVD + c4 * 4);
        }
        __syncthreads();

        float S[4][4];
        #pragma unroll
        for (int a = 0; a < 4; a++)
            #pragma unroll
            for (int c = 0; c < 4; c++) S[a][c] = 0.f;
        #pragma unroll 8
        for (int d = 0; d < 64; d++) {
            float4 qv = *(const float4*)&Qs[d * FST + ty * 4];
            float4 kv = *(const float4*)&Ks[d * FST + tx * 4];
            S[0][0] += qv.x * kv.x; S[0][1] += qv.x * kv.y; S[0][2] += qv.x * kv.z; S[0][3] += qv.x * kv.w;
            S[1][0] += qv.y * kv.x; S[1][1] += qv.y * kv.y; S[1][2] += qv.y * kv.z; S[1][3] += qv.y * kv.w;
            S[2][0] += qv.z * kv.x; S[2][1] += qv.z * kv.y; S[2][2] += qv.z * kv.z; S[2][3] += qv.z * kv.w;
            S[3][0] += qv.w * kv.x; S[3][1] += qv.w * kv.y; S[3][2] += qv.w * kv.z; S[3][3] += qv.w * kv.w;
        }

        #pragma unroll
        for (int a = 0; a < 4; a++) {
            #pragma unroll
            for (int c = 0; c < 4; c++) S[a][c] *= 0.125f;
            float mx = fmaxf(fmaxf(S[a][0], S[a][1]), fmaxf(S[a][2], S[a][3]));
            #pragma unroll
            for (int o = 1; o <= 8; o <<= 1)
                mx = fmaxf(mx, __shfl_xor_sync(0xffffffffu, mx, o));
            float mn = fmaxf(m_i[a], mx);
            float corr = __expf(m_i[a] - mn);
            float rsum = 0.f;
            #pragma unroll
            for (int c = 0; c < 4; c++) {
                float p = __expf(S[a][c] - mn);
                S[a][c] = p; rsum += p;
            }
            #pragma unroll
            for (int o = 1; o <= 8; o <<= 1)
                rsum += __shfl_xor_sync(0xffffffffu, rsum, o);
            l_i[a] = l_i[a] * corr + rsum;
            m_i[a] = mn;
            #pragma unroll
            for (int c = 0; c < 4; c++) O[a][c] *= corr;
            *(float4*)&Ps[(ty * 4 + a) * FST + tx * 4] =
                make_float4(S[a][0], S[a][1], S[a][2], S[a][3]);
        }
        __syncthreads();

        #pragma unroll 4
        for (int k4 = 0; k4 < 16; k4++) {
            float4 pv[4], vv[4];
            #pragma unroll
            for (int a = 0; a < 4; a++)
                pv[a] = *(const float4*)&Ps[(ty * 4 + a) * FST + k4 * 4];
            #pragma unroll
            for (int e = 0; e < 4; e++)
                vv[e] = *(const float4*)&Vs[(k4 * 4 + e) * FST + tx * 4];
            #pragma unroll
            for (int a = 0; a < 4; a++) {
                O[a][0] += pv[a].x * vv[0].x + pv[a].y * vv[1].x + pv[a].z * vv[2].x + pv[a].w * vv[3].x;
                O[a][1] += pv[a].x * vv[0].y + pv[a].y * vv[1].y + pv[a].z * vv[2].y + pv[a].w * vv[3].y;
                O[a][2] += pv[a].x * vv[0].z + pv[a].y * vv[1].z + pv[a].z * vv[2].z + pv[a].w * vv[3].z;
                O[a][3] += pv[a].x * vv[0].w + pv[a].y * vv[1].w + pv[a].z * vv[2].w + pv[a].w * vv[3].w;
            }
        }
    }

    #pragma unroll
    for (int a = 0; a < 4; a++) {
        float inv = 1.f / l_i[a];
        *(float4*)(g_o + (size_t)(b * NM + q0 + ty * 4 + a) * DM + h * HD + tx * 4) =
            make_float4(O[a][0] * inv, O[a][1] * inv, O[a][2] * inv, O[a][3] * inv);
    }
}

// ---------------- unmerge ----------------
__global__ void zero_k(float4* o)
{
    o[(size_t)blockIdx.x * 256 + threadIdx.x] = make_float4(0.f, 0.f, 0.f, 0.f);
}

__global__ void scatter_k(float* __restrict__ out)
{
    int row = blockIdx.x;
    int b = row / NM, m = row % NM;
    int p = g_keep[b * NM + m];
    float4* dst = (float4*)(out + (size_t)(b * NN + p) * DM);
    const float4* src = (const float4*)(g_om + (size_t)row * DM);
    dst[threadIdx.x] = src[threadIdx.x];
}

__global__ void copygab_k(float* __restrict__ out)
{
    int i = blockIdx.x;
    int b = i / RR, t = i % RR;
    int a = g_ga[b * RR + t];
    int g = g_gb[b * RR + t];
    const float4* src = (const float4*)(out + (size_t)(b * NN + a) * DM);
    float4*       dst = (float4*)(out + (size_t)(b * NN + g) * DM);
    dst[threadIdx.x] = src[threadIdx.x];
}

// ---------------- launcher ----------------
extern "C" void kernel_launch(void* const* d_in, const int* in_sizes, int n_in,
                              void* d_out, int out_size)
{
    const float* x  = (const float*)d_in[0];
    const float* fr = (const float*)d_in[1];
    const float* Wq = (const float*)d_in[2];
    const float* Wk = (const float*)d_in[3];
    const float* Wv = (const float*)d_in[4];
    const float* Wo = (const float*)d_in[5];
    float* out = (float*)d_out;

    float *p_metric, *p_xm, *p_q, *p_kb, *p_v, *p_o, *p_om;
    cudaGetSymbolAddress((void**)&p_metric, g_metric);
    cudaGetSymbolAddress((void**)&p_xm,     g_xm);
    cudaGetSymbolAddress((void**)&p_q,      g_q);
    cudaGetSymbolAddress((void**)&p_kb,     g_kb);
    cudaGetSymbolAddress((void**)&p_v,      g_v);
    cudaGetSymbolAddress((void**)&p_o,      g_o);
    cudaGetSymbolAddress((void**)&p_om,     g_om);

    __nv_bfloat16 *xmh, *xml, *oh, *ol, *wqh, *wql, *wkh, *wkl, *wvh, *wvl, *woh, *wol;
    cudaGetSymbolAddress((void**)&xmh, g_xm_h);  cudaGetSymbolAddress((void**)&xml, g_xm_l);
    cudaGetSymbolAddress((void**)&oh,  g_o_h);   cudaGetSymbolAddress((void**)&ol,  g_o_l);
    cudaGetSymbolAddress((void**)&wqh, g_WqT_h); cudaGetSymbolAddress((void**)&wql, g_WqT_l);
    cudaGetSymbolAddress((void**)&wkh, g_WkT_h); cudaGetSymbolAddress((void**)&wkl, g_WkT_l);
    cudaGetSymbolAddress((void**)&wvh, g_WvT_h); cudaGetSymbolAddress((void**)&wvl, g_WvT_l);
    cudaGetSymbolAddress((void**)&woh, g_WoT_h); cudaGetSymbolAddress((void**)&wol, g_WoT_l);

    const int FLASH_SMEM = 4 * 64 * FST * sizeof(float);
    cudaFuncSetAttribute(flash_k, cudaFuncAttributeMaxDynamicSharedMemorySize, FLASH_SMEM);

    // weight transpose+split (independent of data path)
    splitT_k<<<dim3(DM / 32,  DM / 32), dim3(32, 8)>>>(Wq, wqh, wql, DM, DM);
    splitT_k<<<dim3(KVD / 32, DM / 32), dim3(32, 8)>>>(Wk, wkh, wkl, DM, KVD);
    splitT_k<<<dim3(KVD / 32, DM / 32), dim3(32, 8)>>>(Wv, wvh, wvl, DM, KVD);
    splitT_k<<<dim3(DM / 32,  DM / 32), dim3(32, 8)>>>(Wo, woh, wol, DM, DM);

    // selection path — exact fp32, numerics untouched
    gemm_k<<<dim3(KVD / 128, BB * NN / 128), 256>>>(x, Wk, p_metric, BB * NN, KVD, DM);
    normalize_k<<<BB * NN, 256>>>();
    transpose_k<<<dim3(HALF / 32, KVD / 32, BB), dim3(32, 8)>>>();
    score_k<<<dim3(HALF / 16, 4, BB), 256>>>();
    argred_k<<<dim3(HALF / 256, BB), 256>>>();
    select_k<<<BB, 512>>>();
    merge_k<<<MROWS, 256>>>(x);

    // projections on tensor cores (split-bf16 HMMA, ~fp32 accuracy)
    split_k<<<(MROWS * DM / 4 + 255) / 256, 256>>>((const float4*)p_xm, xmh, xml, MROWS * DM / 4);
    hmma_gemm<<<dim3(DM / 128,  MROWS / 128), 256>>>(xmh, xml, wqh, wql, p_q,  MROWS, DM,  DM);
    hmma_gemm<<<dim3(KVD / 128, MROWS / 128), 256>>>(xmh, xml, wkh, wkl, p_kb, MROWS, KVD, DM);
    hmma_gemm<<<dim3(KVD / 128, MROWS / 128), 256>>>(xmh, xml, wvh, wvl, p_v,  MROWS, KVD, DM);

    rope_q_k<<<MROWS, 512>>>(fr);
    rope_k_k<<<MROWS, 128>>>(fr);

    flash_k<<<dim3(NM / 64, BB * NH), 256, FLASH_SMEM>>>();

    split_k<<<(MROWS * DM / 4 + 255) / 256, 256>>>((const float4*)p_o, oh, ol, MROWS * DM / 4);
    hmma_gemm<<<dim3(DM / 128, MROWS / 128), 256>>>(oh, ol, woh, wol, p_om, MROWS, DM, DM);

    zero_k<<<(BB * NN * DM) / 1024, 256>>>((float4*)out);
    scatter_k<<<MROWS, 256>>>(out);
    copygab_k<<<BB * RR, 256>>>(out);
    (void)in_sizes; (void)n_in; (void)out_size;
}

// round 13
// speedup vs baseline: 2.7950x; 1.4473x over previous
#include <cuda_runtime.h>
#include <cuda_bf16.h>
#include <math.h>
#include <stdint.h>

// ---------------- problem constants ----------------
#define BB    2
#define NN    2048
#define DM    1024
#define NH    16
#define NKV   4
#define HD    64
#define RR    256
#define NM    1792          // N - R
#define HALF  1024          // N/2
#define MROWS (BB*NM)       // 3584
#define KVD   (NKV*HD)      // 256

// ---------------- scratch (static device memory) ----------------
__device__ float g_metric[BB*NN*KVD];
__device__ float g_an [BB*HALF*KVD];
__device__ float g_bn [BB*HALF*KVD];
__device__ float g_bnT[BB*KVD*HALF];
__device__ float g_pS[BB*4*HALF];
__device__ int   g_pB[BB*4*HALF];
__device__ float g_bestS[BB*HALF];
__device__ int   g_bestB[BB*HALF];
__device__ int   g_ga[BB*RR];
__device__ int   g_gb[BB*RR];
__device__ int   g_partner[BB*NN];
__device__ int   g_keep[BB*NM];
__device__ float g_xm[(size_t)MROWS*DM];
__device__ float g_q [(size_t)MROWS*DM];
__device__ float g_kb[(size_t)MROWS*KVD];
__device__ float g_v [(size_t)MROWS*KVD];
__device__ float g_om[(size_t)MROWS*DM];
// split-bf16 operands
__device__ __nv_bfloat16 g_xm_h[(size_t)MROWS*DM], g_xm_l[(size_t)MROWS*DM];
__device__ __nv_bfloat16 g_o_h [(size_t)MROWS*DM], g_o_l [(size_t)MROWS*DM];
__device__ __nv_bfloat16 g_q_h [(size_t)MROWS*DM], g_q_l [(size_t)MROWS*DM];
__device__ __nv_bfloat16 g_k_h [(size_t)MROWS*KVD], g_k_l[(size_t)MROWS*KVD];
__device__ __nv_bfloat16 g_v_h [(size_t)MROWS*KVD], g_v_l[(size_t)MROWS*KVD];
__device__ __nv_bfloat16 g_WqT_h[DM*DM],  g_WqT_l[DM*DM];
__device__ __nv_bfloat16 g_WkT_h[KVD*DM], g_WkT_l[KVD*DM];
__device__ __nv_bfloat16 g_WvT_h[KVD*DM], g_WvT_l[KVD*DM];
__device__ __nv_bfloat16 g_WoT_h[DM*DM],  g_WoT_l[DM*DM];

// ================= warp-MMA helpers =================
__device__ __forceinline__ uint32_t smem_u32(const void* p) {
    uint32_t a;
    asm("{ .reg .u64 t; cvta.to.shared.u64 t, %1; cvt.u32.u64 %0, t; }" : "=r"(a) : "l"(p));
    return a;
}
__device__ __forceinline__ void ldsm_x4(uint32_t* r, uint32_t a) {
    asm volatile("ldmatrix.sync.aligned.m8n8.x4.shared.b16 {%0,%1,%2,%3}, [%4];"
                 : "=r"(r[0]), "=r"(r[1]), "=r"(r[2]), "=r"(r[3]) : "r"(a));
}
__device__ __forceinline__ void ldsm_x2(uint32_t* r, uint32_t a) {
    asm volatile("ldmatrix.sync.aligned.m8n8.x2.shared.b16 {%0,%1}, [%2];"
                 : "=r"(r[0]), "=r"(r[1]) : "r"(a));
}
__device__ __forceinline__ void ldsm_x2t(uint32_t* r, uint32_t a) {
    asm volatile("ldmatrix.sync.aligned.m8n8.x2.trans.shared.b16 {%0,%1}, [%2];"
                 : "=r"(r[0]), "=r"(r[1]) : "r"(a));
}
__device__ __forceinline__ void mma16816(float* c, const uint32_t* a, const uint32_t* b) {
    asm volatile(
        "mma.sync.aligned.m16n8k16.row.col.f32.bf16.bf16.f32 "
        "{%0,%1,%2,%3}, {%4,%5,%6,%7}, {%8,%9}, {%0,%1,%2,%3};"
        : "+f"(c[0]), "+f"(c[1]), "+f"(c[2]), "+f"(c[3])
        : "r"(a[0]), "r"(a[1]), "r"(a[2]), "r"(a[3]), "r"(b[0]), "r"(b[1]));
}
__device__ __forceinline__ uint32_t pack2bf(__nv_bfloat16 a, __nv_bfloat16 b) {
    __nv_bfloat162 t = __halves2bfloat162(a, b);
    return *(uint32_t*)&t;
}

// ================= split-bf16 HMMA GEMM (projections) =================
#define BKC 32
#define LDT 40
__global__ void __launch_bounds__(256) hmma_gemm(
    const __nv_bfloat16* __restrict__ Ah, const __nv_bfloat16* __restrict__ Al,
    const __nv_bfloat16* __restrict__ Bh, const __nv_bfloat16* __restrict__ Bl,
    float* __restrict__ C, int M, int N, int K)
{
    __shared__ __nv_bfloat16 As_h[128][LDT], As_l[128][LDT];
    __shared__ __nv_bfloat16 Bs_h[128][LDT], Bs_l[128][LDT];
    const int tid = threadIdx.x, lane = tid & 31, wid = tid >> 5;
    const int wm = (wid & 1) * 64;
    const int wn = (wid >> 1) * 32;
    const int m0 = blockIdx.y * 128, n0 = blockIdx.x * 128;

    float acc[4][4][4];
    #pragma unroll
    for (int i = 0; i < 4; i++)
        #pragma unroll
        for (int j = 0; j < 4; j++)
            #pragma unroll
            for (int q = 0; q < 4; q++) acc[i][j][q] = 0.f;

    for (int kc = 0; kc < K; kc += BKC) {
        #pragma unroll
        for (int i = 0; i < 2; i++) {
            int s = tid + i * 256;
            int r = s >> 2;
            int u = (s & 3) * 8;
            *(uint4*)&As_h[r][u] = *(const uint4*)(Ah + (size_t)(m0 + r) * K + kc + u);
            *(uint4*)&As_l[r][u] = *(const uint4*)(Al + (size_t)(m0 + r) * K + kc + u);
            *(uint4*)&Bs_h[r][u] = *(const uint4*)(Bh + (size_t)(n0 + r) * K + kc + u);
            *(uint4*)&Bs_l[r][u] = *(const uint4*)(Bl + (size_t)(n0 + r) * K + kc + u);
        }
        __syncthreads();
        #pragma unroll
        for (int ks = 0; ks < 2; ks++) {
            uint32_t bh[4][2], bl[4][2];
            #pragma unroll
            for (int nt = 0; nt < 4; nt++) {
                int nrow = wn + nt * 8 + (lane & 7);
                int kcol = ks * 16 + ((lane >> 3) & 1) * 8;
                ldsm_x2(bh[nt], smem_u32(&Bs_h[nrow][kcol]));
                ldsm_x2(bl[nt], smem_u32(&Bs_l[nrow][kcol]));
            }
            #pragma unroll
            for (int mt = 0; mt < 4; mt++) {
                int arow = wm + mt * 16 + (lane & 15);
                int acol = ks * 16 + (lane >> 4) * 8;
                uint32_t ah[4], al[4];
                ldsm_x4(ah, smem_u32(&As_h[arow][acol]));
                ldsm_x4(al, smem_u32(&As_l[arow][acol]));
                #pragma unroll
                for (int nt = 0; nt < 4; nt++) {
                    mma16816(acc[mt][nt], ah, bh[nt]);
                    mma16816(acc[mt][nt], ah, bl[nt]);
                    mma16816(acc[mt][nt], al, bh[nt]);
                }
            }
        }
        __syncthreads();
    }
    #pragma unroll
    for (int mt = 0; mt < 4; mt++) {
        #pragma unroll
        for (int nt = 0; nt < 4; nt++) {
            int row = m0 + wm + mt * 16 + (lane >> 2);
            int col = n0 + wn + nt * 8 + (lane & 3) * 2;
            *(float2*)(C + (size_t)row * N + col)       = make_float2(acc[mt][nt][0], acc[mt][nt][1]);
            *(float2*)(C + (size_t)(row + 8) * N + col) = make_float2(acc[mt][nt][2], acc[mt][nt][3]);
        }
    }
}

// ---------------- split fp32 -> (hi, lo) bf16 ----------------
__global__ void split_k(const float4* __restrict__ in,
                        __nv_bfloat16* __restrict__ hi, __nv_bfloat16* __restrict__ lo, int n4)
{
    int i = blockIdx.x * 256 + threadIdx.x;
    if (i >= n4) return;
    float4 v = in[i];
    __nv_bfloat16 h0 = __float2bfloat16(v.x), h1 = __float2bfloat16(v.y);
    __nv_bfloat16 h2 = __float2bfloat16(v.z), h3 = __float2bfloat16(v.w);
    __nv_bfloat16 l0 = __float2bfloat16(v.x - __bfloat162float(h0));
    __nv_bfloat16 l1 = __float2bfloat16(v.y - __bfloat162float(h1));
    __nv_bfloat16 l2 = __float2bfloat16(v.z - __bfloat162float(h2));
    __nv_bfloat16 l3 = __float2bfloat16(v.w - __bfloat162float(h3));
    __nv_bfloat162* H = (__nv_bfloat162*)hi;
    __nv_bfloat162* L = (__nv_bfloat162*)lo;
    H[2*i]   = __halves2bfloat162(h0, h1);
    H[2*i+1] = __halves2bfloat162(h2, h3);
    L[2*i]   = __halves2bfloat162(l0, l1);
    L[2*i+1] = __halves2bfloat162(l2, l3);
}

// ---------------- transpose + split: W[K][N] -> WT_hi/lo[N][K] ----------------
__global__ void splitT_k(const float* __restrict__ W,
                         __nv_bfloat16* __restrict__ Th, __nv_bfloat16* __restrict__ Tl,
                         int K, int N)
{
    __shared__ float t[32][33];
    int k0 = blockIdx.y * 32, n0 = blockIdx.x * 32;
    int tx = threadIdx.x, ty = threadIdx.y;
    for (int i = ty; i < 32; i += 8)
        t[i][tx] = W[(size_t)(k0 + i) * N + n0 + tx];
    __syncthreads();
    for (int i = ty; i < 32; i += 8) {
        float v = t[tx][i];
        __nv_bfloat16 h = __float2bfloat16(v);
        size_t o = (size_t)(n0 + i) * K + k0 + tx;
        Th[o] = h;
        Tl[o] = __float2bfloat16(v - __bfloat162float(h));
    }
}

// ---------------- generic fp32 SGEMM (selection path only — bit-exact) ------
__global__ void __launch_bounds__(256)
gemm_k(const float* __restrict__ A, const float* __restrict__ B,
       float* __restrict__ C, int M, int N, int K)
{
    const int BK = 16;
    __shared__ float As[16][132];
    __shared__ float Bs[16][132];
    const int tid = threadIdx.x;
    const int tx  = tid & 15;
    const int ty  = tid >> 4;
    const int m0  = blockIdx.y * 128;
    const int n0  = blockIdx.x * 128;

    float acc[8][8];
    #pragma unroll
    for (int i = 0; i < 8; i++)
        #pragma unroll
        for (int j = 0; j < 8; j++) acc[i][j] = 0.f;

    for (int k0 = 0; k0 < K; k0 += BK) {
        #pragma unroll
        for (int i = 0; i < 2; i++) {
            int s  = tid + i * 256;
            int r  = s >> 2;
            int kc = (s & 3) * 4;
            float4 v = *(const float4*)(A + (size_t)(m0 + r) * K + k0 + kc);
            As[kc + 0][r] = v.x; As[kc + 1][r] = v.y;
            As[kc + 2][r] = v.z; As[kc + 3][r] = v.w;
        }
        #pragma unroll
        for (int i = 0; i < 2; i++) {
            int s = tid + i * 256;
            int r = s >> 5;
            int c = (s & 31) * 4;
            *(float4*)&Bs[r][c] = *(const float4*)(B + (size_t)(k0 + r) * N + n0 + c);
        }
        __syncthreads();
        #pragma unroll
        for (int kk = 0; kk < BK; kk++) {
            float ra[8], rb[8];
            *(float4*)&ra[0] = *(const float4*)&As[kk][ty * 8];
            *(float4*)&ra[4] = *(const float4*)&As[kk][ty * 8 + 4];
            *(float4*)&rb[0] = *(const float4*)&Bs[kk][tx * 8];
            *(float4*)&rb[4] = *(const float4*)&Bs[kk][tx * 8 + 4];
            #pragma unroll
            for (int i = 0; i < 8; i++)
                #pragma unroll
                for (int j = 0; j < 8; j++) acc[i][j] += ra[i] * rb[j];
        }
        __syncthreads();
    }
    #pragma unroll
    for (int i = 0; i < 8; i++) {
        size_t cr = (size_t)(m0 + ty * 8 + i) * N + n0 + tx * 8;
        *(float4*)(C + cr)     = make_float4(acc[i][0], acc[i][1], acc[i][2], acc[i][3]);
        *(float4*)(C + cr + 4) = make_float4(acc[i][4], acc[i][5], acc[i][6], acc[i][7]);
    }
}

// ---------------- normalize metric rows into an (even) / bn (odd) ----------------
__global__ void normalize_k()
{
    __shared__ float wsum[8];
    __shared__ float total;
    int row = blockIdx.x, t = threadIdx.x;
    float v = g_metric[(size_t)row * KVD + t];
    float ss = v * v;
    #pragma unroll
    for (int o = 16; o; o >>= 1) ss += __shfl_xor_sync(0xffffffffu, ss, o);
    if ((t & 31) == 0) wsum[t >> 5] = ss;
    __syncthreads();
    if (t == 0) {
        float s2 = 0.f;
        #pragma unroll
        for (int i = 0; i < 8; i++) s2 += wsum[i];
        total = fmaxf(sqrtf(s2), 1e-12f);
    }
    __syncthreads();
    float outv = v / total;
    int b = row >> 11, i = row & 2047;
    if (i & 1) g_bn[((size_t)b * HALF + (i >> 1)) * KVD + t] = outv;
    else       g_an[((size_t)b * HALF + (i >> 1)) * KVD + t] = outv;
}

// ---------------- transpose bn (1024x256) -> bnT (256x1024) per batch ----------------
__global__ void transpose_k()
{
    __shared__ float tile[32][33];
    int b  = blockIdx.z;
    int j0 = blockIdx.x * 32;
    int d0 = blockIdx.y * 32;
    for (int i = threadIdx.y; i < 32; i += 8)
        tile[i][threadIdx.x] = g_bn[((size_t)b * HALF + j0 + i) * KVD + d0 + threadIdx.x];
    __syncthreads();
    for (int i = threadIdx.y; i < 32; i += 8)
        g_bnT[((size_t)b * KVD + d0 + i) * HALF + j0 + threadIdx.x] = tile[threadIdx.x][i];
}

// ---------------- scores + per-a-row partial argmax, j-chunked (bit-exact) ---
__global__ void __launch_bounds__(256) score_k()
{
    __shared__ float a_s[16][256];
    __shared__ float rs[256];
    __shared__ int   rj[256];
    int b   = blockIdx.z;
    int jc  = blockIdx.y;
    int a0  = blockIdx.x * 16;
    int tid = threadIdx.x;

    #pragma unroll
    for (int i = 0; i < 4; i++) {
        int s = tid + i * 256;
        int r = s >> 6;
        int c4 = s & 63;
        *(float4*)&a_s[r][c4 * 4] =
            *(const float4*)(g_an + ((size_t)b * HALF + a0 + r) * KVD + c4 * 4);
    }
    __syncthreads();

    const float* bt = g_bnT + (size_t)b * KVD * HALF;
    int j = jc * 256 + tid;
    float acc[16];
    #pragma unroll
    for (int i = 0; i < 16; i++) acc[i] = 0.f;
    #pragma unroll 4
    for (int d4 = 0; d4 < 64; d4++) {
        float b0 = bt[(d4 * 4 + 0) * HALF + j];
        float b1 = bt[(d4 * 4 + 1) * HALF + j];
        float b2 = bt[(d4 * 4 + 2) * HALF + j];
        float b3 = bt[(d4 * 4 + 3) * HALF + j];
        #pragma unroll
        for (int i = 0; i < 16; i++) {
            float4 a4 = *(const float4*)&a_s[i][d4 * 4];
            acc[i] += a4.x * b0 + a4.y * b1 + a4.z * b2 + a4.w * b3;
        }
    }

    for (int i = 0; i < 16; i++) {
        rs[tid] = acc[i]; rj[tid] = j;
        __syncthreads();
        for (int s = 128; s > 0; s >>= 1) {
            if (tid < s) {
                float s2 = rs[tid + s]; int j2 = rj[tid + s];
                if (s2 > rs[tid] || (s2 == rs[tid] && j2 < rj[tid])) {
                    rs[tid] = s2; rj[tid] = j2;
                }
            }
            __syncthreads();
        }
        if (tid == 0) {
            g_pS[(b * 4 + jc) * HALF + a0 + i] = rs[0];
            g_pB[(b * 4 + jc) * HALF + a0 + i] = rj[0];
        }
        __syncthreads();
    }
}

// ---------------- reduce chunk partials -> bestS/bestB ----------------
__global__ void argred_k()
{
    int b = blockIdx.y;
    int a = blockIdx.x * 256 + threadIdx.x;
    float bs = -1e30f; int bj = 0;
    #pragma unroll
    for (int c = 0; c < 4; c++) {
        float s = g_pS[(b * 4 + c) * HALF + a];
        int   j = g_pB[(b * 4 + c) * HALF + a];
        if (s > bs) { bs = s; bj = j; }
    }
    g_bestS[b * HALF + a] = bs;
    g_bestB[b * HALF + a] = bj;
}

// ---------------- sort + greedy select + keep/partner ----------------
__global__ void __launch_bounds__(512) select_k()
{
    __shared__ float key[1024];
    __shared__ int   aid[1024];
    __shared__ int   bb[1024];
    __shared__ unsigned char used[1024];
    __shared__ unsigned char mask[2048];
    __shared__ int ga[256], gb[256];
    __shared__ int keepb[NM];
    int b = blockIdx.x, tid = threadIdx.x;

    for (int i = tid; i < 1024; i += 512) {
        key[i]  = g_bestS[b * HALF + i];
        aid[i]  = i;
        bb[i]   = g_bestB[b * HALF + i];
        used[i] = 0;
    }
    for (int i = tid; i < 2048; i += 512) mask[i] = 1;
    __syncthreads();

    for (int k = 2; k <= 1024; k <<= 1) {
        for (int j = k >> 1; j > 0; j >>= 1) {
            int t   = tid;
            int idx = ((t & ~(j - 1)) << 1) | (t & (j - 1));
            int ixj = idx | j;
            bool desc = ((idx & k) == 0);
            float ki = key[idx], kj = key[ixj];
            int   ai = aid[idx], aj = aid[ixj];
            bool ibetter = (ki > kj) || (ki == kj && ai < aj);
            bool dos = desc ? !ibetter : ibetter;
            if (dos) { key[idx] = kj; key[ixj] = ki; aid[idx] = aj; aid[ixj] = ai; }
            __syncthreads();
        }
    }

    if (tid == 0) {
        int cnt = 0;
        for (int t = 0; t < 1024 && cnt < RR; t++) {
            int a  = aid[t];
            int bl = bb[a];
            if (!used[bl]) {
                used[bl] = 1;
                ga[cnt] = 2 * a;
                gb[cnt] = 2 * bl + 1;
                cnt++;
            }
        }
        if (cnt == 0) { ga[0] = 0; gb[0] = 1; cnt = 1; }
        for (int t = cnt; t < RR; t++) { ga[t] = ga[0]; gb[t] = gb[0]; }
        for (int t = 0; t < RR; t++) mask[gb[t]] = 0;
        int c2 = 0;
        for (int p = 0; p < NN && c2 < NM; p++)
            if (mask[p]) keepb[c2++] = p;
    }
    __syncthreads();

    for (int i = tid; i < NN; i += 512) g_partner[b * NN + i] = -1;
    for (int i = tid; i < NM; i += 512) g_keep[b * NM + i] = keepb[i];
    if (tid < RR) { g_ga[b * RR + tid] = ga[tid]; g_gb[b * RR + tid] = gb[tid]; }
    __syncthreads();
    if (tid < RR) g_partner[b * NN + ga[tid]] = gb[tid];
}

// ---------------- merge: build x_m ----------------
__global__ void merge_k(const float* __restrict__ x)
{
    int row = blockIdx.x;
    int b = row / NM, m = row % NM;
    int p  = g_keep[b * NM + m];
    int pr = g_partner[b * NN + p];
    const float4* xs = (const float4*)(x + (size_t)(b * NN + p) * DM);
    float4* dst = (float4*)(g_xm + (size_t)row * DM);
    int t = threadIdx.x;
    if (pr < 0) {
        dst[t] = xs[t];
    } else {
        const float4* xb2 = (const float4*)(x + (size_t)(b * NN + pr) * DM);
        float4 u = xs[t], w = xb2[t];
        dst[t] = make_float4((u.x + w.x) * 0.5f, (u.y + w.y) * 0.5f,
                             (u.z + w.z) * 0.5f, (u.w + w.w) * 0.5f);
    }
}

// ---------------- RoPE + split to bf16 hi/lo ----------------
__global__ void rope_split_q(const float* __restrict__ fr)
{
    int row = blockIdx.x;
    int m = row % NM;
    int t = threadIdx.x;                  // 512 pairs
    int jp = t & 31;
    float c = fr[m * 64 + 2 * jp];
    float s = fr[m * 64 + 2 * jp + 1];
    float2 v = ((const float2*)(g_q + (size_t)row * DM))[t];
    float r0 = v.x * c - v.y * s, r1 = v.x * s + v.y * c;
    __nv_bfloat16 h0 = __float2bfloat16(r0), h1 = __float2bfloat16(r1);
    ((__nv_bfloat162*)g_q_h)[(size_t)row * 512 + t] = __halves2bfloat162(h0, h1);
    ((__nv_bfloat162*)g_q_l)[(size_t)row * 512 + t] = __halves2bfloat162(
        __float2bfloat16(r0 - __bfloat162float(h0)),
        __float2bfloat16(r1 - __bfloat162float(h1)));
}

__global__ void rope_split_kk(const float* __restrict__ fr)
{
    int row = blockIdx.x;
    int m = row % NM;
    int t = threadIdx.x;                  // 128 pairs
    int jp = t & 31;
    float c = fr[m * 64 + 2 * jp];
    float s = fr[m * 64 + 2 * jp + 1];
    float2 v = ((const float2*)(g_kb + (size_t)row * KVD))[t];
    float r0 = v.x * c - v.y * s, r1 = v.x * s + v.y * c;
    __nv_bfloat16 h0 = __float2bfloat16(r0), h1 = __float2bfloat16(r1);
    ((__nv_bfloat162*)g_k_h)[(size_t)row * 128 + t] = __halves2bfloat162(h0, h1);
    ((__nv_bfloat162*)g_k_l)[(size_t)row * 128 + t] = __halves2bfloat162(
        __float2bfloat16(r0 - __bfloat162float(h0)),
        __float2bfloat16(r1 - __bfloat162float(h1)));
}

// ---------------- HMMA flash attention (128q x 64k tiles, d=64, split-bf16) --
#define FLT 72
#define FQ_BYTES (128*FLT*2)   // 18432
#define FK_BYTES (64*FLT*2)    // 9216
#define FLASH_SMEM (2*FQ_BYTES + 4*FK_BYTES)  // 73728
__global__ void __launch_bounds__(256) flashmma_k()
{
    extern __shared__ char smc[];
    __nv_bfloat16* Qh = (__nv_bfloat16*)smc;
    __nv_bfloat16* Ql = (__nv_bfloat16*)(smc + FQ_BYTES);
    __nv_bfloat16* Kh = (__nv_bfloat16*)(smc + 2*FQ_BYTES);
    __nv_bfloat16* Kl = (__nv_bfloat16*)(smc + 2*FQ_BYTES + FK_BYTES);
    __nv_bfloat16* Vh = (__nv_bfloat16*)(smc + 2*FQ_BYTES + 2*FK_BYTES);
    __nv_bfloat16* Vl = (__nv_bfloat16*)(smc + 2*FQ_BYTES + 3*FK_BYTES);

    int bh = blockIdx.y;
    int b = bh >> 4, h = bh & 15, kh = h >> 2;
    int q0 = blockIdx.x * 128;
    int tid = threadIdx.x, lane = tid & 31, wid = tid >> 5;

    // load Q tile (128 x 64) hi/lo
    #pragma unroll
    for (int i = 0; i < 4; i++) {
        int s = tid + i * 256;            // 0..1023
        int r = s >> 3, c8 = (s & 7) * 8;
        size_t go = (size_t)(b * NM + q0 + r) * DM + h * HD + c8;
        *(uint4*)&Qh[r * FLT + c8] = *(const uint4*)(g_q_h + go);
        *(uint4*)&Ql[r * FLT + c8] = *(const uint4*)(g_q_l + go);
    }

    float m0 = -1e30f, m1 = -1e30f, l0 = 0.f, l1 = 0.f;
    float O[8][4];
    #pragma unroll
    for (int d = 0; d < 8; d++)
        #pragma unroll
        for (int q = 0; q < 4; q++) O[d][q] = 0.f;

    for (int kt = 0; kt < NM / 64; kt++) {
        __syncthreads();
        #pragma unroll
        for (int i = 0; i < 2; i++) {
            int s = tid + i * 256;        // 0..511
            int r = s >> 3, c8 = (s & 7) * 8;
            size_t go = (size_t)(b * NM + kt * 64 + r) * KVD + kh * HD + c8;
            *(uint4*)&Kh[r * FLT + c8] = *(const uint4*)(g_k_h + go);
            *(uint4*)&Kl[r * FLT + c8] = *(const uint4*)(g_k_l + go);
            *(uint4*)&Vh[r * FLT + c8] = *(const uint4*)(g_v_h + go);
            *(uint4*)&Vl[r * FLT + c8] = *(const uint4*)(g_v_l + go);
        }
        __syncthreads();

        // ---- S = Q K^T (split 3-term) ----
        float S[8][4];
        #pragma unroll
        for (int nt = 0; nt < 8; nt++)
            #pragma unroll
            for (int q = 0; q < 4; q++) S[nt][q] = 0.f;
        #pragma unroll
        for (int ks = 0; ks < 4; ks++) {
            uint32_t qh4[4], ql4[4];
            uint32_t aaddr = smem_u32(&Qh[(wid * 16 + (lane & 15)) * FLT + ks * 16 + (lane >> 4) * 8]);
            ldsm_x4(qh4, aaddr);
            ldsm_x4(ql4, aaddr + FQ_BYTES);   // Ql at fixed byte offset from Qh
            #pragma unroll
            for (int nt = 0; nt < 8; nt++) {
                uint32_t kh2[2], kl2[2];
                uint32_t baddr = smem_u32(&Kh[(nt * 8 + (lane & 7)) * FLT + ks * 16 + ((lane >> 3) & 1) * 8]);
                ldsm_x2(kh2, baddr);
                ldsm_x2(kl2, baddr + FK_BYTES);
                mma16816(S[nt], qh4, kh2);
                mma16816(S[nt], qh4, kl2);
                mma16816(S[nt], ql4, kh2);
            }
        }

        // ---- online softmax (rows r0 = lane>>2, r1 = r0+8 of warp tile) ----
        float mx0 = -1e30f, mx1 = -1e30f;
        #pragma unroll
        for (int nt = 0; nt < 8; nt++) {
            S[nt][0] *= 0.125f; S[nt][1] *= 0.125f;
            S[nt][2] *= 0.125f; S[nt][3] *= 0.125f;
            mx0 = fmaxf(mx0, fmaxf(S[nt][0], S[nt][1]));
            mx1 = fmaxf(mx1, fmaxf(S[nt][2], S[nt][3]));
        }
        mx0 = fmaxf(mx0, __shfl_xor_sync(0xffffffffu, mx0, 1));
        mx0 = fmaxf(mx0, __shfl_xor_sync(0xffffffffu, mx0, 2));
        mx1 = fmaxf(mx1, __shfl_xor_sync(0xffffffffu, mx1, 1));
        mx1 = fmaxf(mx1, __shfl_xor_sync(0xffffffffu, mx1, 2));
        float mn0 = fmaxf(m0, mx0), mn1 = fmaxf(m1, mx1);
        float c0 = __expf(m0 - mn0), c1 = __expf(m1 - mn1);
        float rs0 = 0.f, rs1 = 0.f;
        #pragma unroll
        for (int nt = 0; nt < 8; nt++) {
            S[nt][0] = __expf(S[nt][0] - mn0); rs0 += S[nt][0];
            S[nt][1] = __expf(S[nt][1] - mn0); rs0 += S[nt][1];
            S[nt][2] = __expf(S[nt][2] - mn1); rs1 += S[nt][2];
            S[nt][3] = __expf(S[nt][3] - mn1); rs1 += S[nt][3];
        }
        rs0 += __shfl_xor_sync(0xffffffffu, rs0, 1);
        rs0 += __shfl_xor_sync(0xffffffffu, rs0, 2);
        rs1 += __shfl_xor_sync(0xffffffffu, rs1, 1);
        rs1 += __shfl_xor_sync(0xffffffffu, rs1, 2);
        l0 = l0 * c0 + rs0; l1 = l1 * c1 + rs1;
        m0 = mn0; m1 = mn1;
        #pragma unroll
        for (int d = 0; d < 8; d++) {
            O[d][0] *= c0; O[d][1] *= c0;
            O[d][2] *= c1; O[d][3] *= c1;
        }

        // ---- split P to bf16 hi/lo (C-frag -> A-frag reuse) ----
        uint32_t Ph[8][2], Pl[8][2];
        #pragma unroll
        for (int nt = 0; nt < 8; nt++) {
            __nv_bfloat16 h0 = __float2bfloat16(S[nt][0]), h1 = __float2bfloat16(S[nt][1]);
            __nv_bfloat16 h2 = __float2bfloat16(S[nt][2]), h3 = __float2bfloat16(S[nt][3]);
            Ph[nt][0] = pack2bf(h0, h1);
            Ph[nt][1] = pack2bf(h2, h3);
            Pl[nt][0] = pack2bf(__float2bfloat16(S[nt][0] - __bfloat162float(h0)),
                                __float2bfloat16(S[nt][1] - __bfloat162float(h1)));
            Pl[nt][1] = pack2bf(__float2bfloat16(S[nt][2] - __bfloat162float(h2)),
                                __float2bfloat16(S[nt][3] - __bfloat162float(h3)));
        }

        // ---- O += P V (split 3-term; V via ldmatrix.trans) ----
        #pragma unroll
        for (int kt2 = 0; kt2 < 4; kt2++) {
            uint32_t ah[4] = { Ph[2*kt2][0], Ph[2*kt2][1], Ph[2*kt2+1][0], Ph[2*kt2+1][1] };
            uint32_t al[4] = { Pl[2*kt2][0], Pl[2*kt2][1], Pl[2*kt2+1][0], Pl[2*kt2+1][1] };
            #pragma unroll
            for (int dt = 0; dt < 8; dt++) {
                uint32_t vh2[2], vl2[2];
                uint32_t vaddr = smem_u32(&Vh[(kt2 * 16 + (lane & 15)) * FLT + dt * 8]);
                ldsm_x2t(vh2, vaddr);
                ldsm_x2t(vl2, vaddr + FK_BYTES);
                mma16816(O[dt], ah, vh2);
                mma16816(O[dt], ah, vl2);
                mma16816(O[dt], al, vh2);
            }
        }
    }

    // ---- epilogue: o = O/l, split to bf16 hi/lo, store ----
    float inv0 = 1.f / l0, inv1 = 1.f / l1;
    int r0 = q0 + wid * 16 + (lane >> 2);
    int col = h * HD + (lane & 3) * 2;
    #pragma unroll
    for (int dt = 0; dt < 8; dt++) {
        float f0 = O[dt][0] * inv0, f1 = O[dt][1] * inv0;
        float f2 = O[dt][2] * inv1, f3 = O[dt][3] * inv1;
        __nv_bfloat16 h0 = __float2bfloat16(f0), h1 = __float2bfloat16(f1);
        __nv_bfloat16 h2 = __float2bfloat16(f2), h3 = __float2bfloat16(f3);
        size_t o0 = (size_t)(b * NM + r0) * DM + col + dt * 8;
        size_t o1 = (size_t)(b * NM + r0 + 8) * DM + col + dt * 8;
        *(__nv_bfloat162*)(g_o_h + o0) = __halves2bfloat162(h0, h1);
        *(__nv_bfloat162*)(g_o_h + o1) = __halves2bfloat162(h2, h3);
        *(__nv_bfloat162*)(g_o_l + o0) = __halves2bfloat162(
            __float2bfloat16(f0 - __bfloat162float(h0)), __float2bfloat16(f1 - __bfloat162float(h1)));
        *(__nv_bfloat162*)(g_o_l + o1) = __halves2bfloat162(
            __float2bfloat16(f2 - __bfloat162float(h2)), __float2bfloat16(f3 - __bfloat162float(h3)));
    }
}

// ---------------- unmerge ----------------
__global__ void zero_k(float4* o)
{
    o[(size_t)blockIdx.x * 256 + threadIdx.x] = make_float4(0.f, 0.f, 0.f, 0.f);
}

__global__ void scatter_k(float* __restrict__ out)
{
    int row = blockIdx.x;
    int b = row / NM, m = row % NM;
    int p = g_keep[b * NM + m];
    float4* dst = (float4*)(out + (size_t)(b * NN + p) * DM);
    const float4* src = (const float4*)(g_om + (size_t)row * DM);
    dst[threadIdx.x] = src[threadIdx.x];
}

__global__ void copygab_k(float* __restrict__ out)
{
    int i = blockIdx.x;
    int b = i / RR, t = i % RR;
    int a = g_ga[b * RR + t];
    int g = g_gb[b * RR + t];
    const float4* src = (const float4*)(out + (size_t)(b * NN + a) * DM);
    float4*       dst = (float4*)(out + (size_t)(b * NN + g) * DM);
    dst[threadIdx.x] = src[threadIdx.x];
}

// ---------------- launcher ----------------
extern "C" void kernel_launch(void* const* d_in, const int* in_sizes, int n_in,
                              void* d_out, int out_size)
{
    const float* x  = (const float*)d_in[0];
    const float* fr = (const float*)d_in[1];
    const float* Wq = (const float*)d_in[2];
    const float* Wk = (const float*)d_in[3];
    const float* Wv = (const float*)d_in[4];
    const float* Wo = (const float*)d_in[5];
    float* out = (float*)d_out;

    float *p_metric, *p_xm, *p_q, *p_kb, *p_v, *p_om;
    cudaGetSymbolAddress((void**)&p_metric, g_metric);
    cudaGetSymbolAddress((void**)&p_xm,     g_xm);
    cudaGetSymbolAddress((void**)&p_q,      g_q);
    cudaGetSymbolAddress((void**)&p_kb,     g_kb);
    cudaGetSymbolAddress((void**)&p_v,      g_v);
    cudaGetSymbolAddress((void**)&p_om,     g_om);

    __nv_bfloat16 *xmh, *xml, *oh, *ol, *vh, *vl;
    __nv_bfloat16 *wqh, *wql, *wkh, *wkl, *wvh, *wvl, *woh, *wol;
    cudaGetSymbolAddress((void**)&xmh, g_xm_h);  cudaGetSymbolAddress((void**)&xml, g_xm_l);
    cudaGetSymbolAddress((void**)&oh,  g_o_h);   cudaGetSymbolAddress((void**)&ol,  g_o_l);
    cudaGetSymbolAddress((void**)&vh,  g_v_h);   cudaGetSymbolAddress((void**)&vl,  g_v_l);
    cudaGetSymbolAddress((void**)&wqh, g_WqT_h); cudaGetSymbolAddress((void**)&wql, g_WqT_l);
    cudaGetSymbolAddress((void**)&wkh, g_WkT_h); cudaGetSymbolAddress((void**)&wkl, g_WkT_l);
    cudaGetSymbolAddress((void**)&wvh, g_WvT_h); cudaGetSymbolAddress((void**)&wvl, g_WvT_l);
    cudaGetSymbolAddress((void**)&woh, g_WoT_h); cudaGetSymbolAddress((void**)&wol, g_WoT_l);

    cudaFuncSetAttribute(flashmma_k, cudaFuncAttributeMaxDynamicSharedMemorySize, FLASH_SMEM);

    // weight transpose+split
    splitT_k<<<dim3(DM / 32,  DM / 32), dim3(32, 8)>>>(Wq, wqh, wql, DM, DM);
    splitT_k<<<dim3(KVD / 32, DM / 32), dim3(32, 8)>>>(Wk, wkh, wkl, DM, KVD);
    splitT_k<<<dim3(KVD / 32, DM / 32), dim3(32, 8)>>>(Wv, wvh, wvl, DM, KVD);
    splitT_k<<<dim3(DM / 32,  DM / 32), dim3(32, 8)>>>(Wo, woh, wol, DM, DM);

    // selection path — exact fp32, numerics untouched
    gemm_k<<<dim3(KVD / 128, BB * NN / 128), 256>>>(x, Wk, p_metric, BB * NN, KVD, DM);
    normalize_k<<<BB * NN, 256>>>();
    transpose_k<<<dim3(HALF / 32, KVD / 32, BB), dim3(32, 8)>>>();
    score_k<<<dim3(HALF / 16, 4, BB), 256>>>();
    argred_k<<<dim3(HALF / 256, BB), 256>>>();
    select_k<<<BB, 512>>>();
    merge_k<<<MROWS, 256>>>(x);

    // projections (split-bf16 HMMA)
    split_k<<<(MROWS * DM / 4 + 255) / 256, 256>>>((const float4*)p_xm, xmh, xml, MROWS * DM / 4);
    hmma_gemm<<<dim3(DM / 128,  MROWS / 128), 256>>>(xmh, xml, wqh, wql, p_q,  MROWS, DM,  DM);
    hmma_gemm<<<dim3(KVD / 128, MROWS / 128), 256>>>(xmh, xml, wkh, wkl, p_kb, MROWS, KVD, DM);
    hmma_gemm<<<dim3(KVD / 128, MROWS / 128), 256>>>(xmh, xml, wvh, wvl, p_v,  MROWS, KVD, DM);

    // rope + split to bf16
    rope_split_q<<<MROWS, 512>>>(fr);
    rope_split_kk<<<MROWS, 128>>>(fr);
    split_k<<<(MROWS * KVD / 4 + 255) / 256, 256>>>((const float4*)p_v, vh, vl, MROWS * KVD / 4);

    // flash attention (HMMA, split-bf16)
    flashmma_k<<<dim3(NM / 128, BB * NH), 256, FLASH_SMEM>>>();

    // output projection (reads oh/ol written by flash)
    hmma_gemm<<<dim3(DM / 128, MROWS / 128), 256>>>(oh, ol, woh, wol, p_om, MROWS, DM, DM);

    zero_k<<<(BB * NN * DM) / 1024, 256>>>((float4*)out);
    scatter_k<<<MROWS, 256>>>(out);
    copygab_k<<<BB * RR, 256>>>(out);
    (void)in_sizes; (void)n_in; (void)out_size;
}